// round 1
// baseline (speedup 1.0000x reference)
#include <cuda_runtime.h>
#include <math.h>

#define B_SZ   4
#define L_SEQ  2048
#define E_DIM  2048
#define NH     16
#define HD     128
#define M_TOTAL (B_SZ * L_SEQ)   /* 8192 */
#define K_DIM   E_DIM            /* 2048 */
#define N_TOTAL (3 * E_DIM)      /* 6144 */

// Scratch for QKV projection output: [M_TOTAL][N_TOTAL] fp32 (~201 MB).
__device__ float g_y[(size_t)M_TOTAL * (size_t)N_TOTAL];

// ---------------------------------------------------------------------------
// Kernel 1: QKV GEMM  y[m][n] = sum_k x[m][k] * W[n][k] + b[n]
// 128x128 block tile, BK=16, 256 threads, 8x8 per-thread fragment.
// ---------------------------------------------------------------------------
__global__ __launch_bounds__(256) void qkv_gemm_kernel(
    const float* __restrict__ A,      // [M_TOTAL][K_DIM]
    const float* __restrict__ Wt,     // [N_TOTAL][K_DIM]
    const float* __restrict__ bias)   // [N_TOTAL]
{
    __shared__ __align__(16) float As[16][132];
    __shared__ __align__(16) float Bs[16][132];

    const int tid = threadIdx.x;
    const int tx  = tid & 15;
    const int ty  = tid >> 4;
    const int m0  = blockIdx.y * 128;
    const int n0  = blockIdx.x * 128;

    float acc[8][8];
#pragma unroll
    for (int i = 0; i < 8; i++)
#pragma unroll
        for (int j = 0; j < 8; j++) acc[i][j] = 0.f;

    for (int k0 = 0; k0 < K_DIM; k0 += 16) {
#pragma unroll
        for (int u = 0; u < 2; u++) {
            int f = tid * 2 + u;          // float4 id in [0,512)
            int r = f >> 2;               // tile row 0..127
            int c = (f & 3) << 2;         // tile col 0,4,8,12
            float4 av = *(const float4*)&A [(size_t)(m0 + r) * K_DIM + k0 + c];
            As[c + 0][r] = av.x; As[c + 1][r] = av.y;
            As[c + 2][r] = av.z; As[c + 3][r] = av.w;
            float4 bv = *(const float4*)&Wt[(size_t)(n0 + r) * K_DIM + k0 + c];
            Bs[c + 0][r] = bv.x; Bs[c + 1][r] = bv.y;
            Bs[c + 2][r] = bv.z; Bs[c + 3][r] = bv.w;
        }
        __syncthreads();
#pragma unroll
        for (int kk = 0; kk < 16; kk++) {
            float4 a0 = *(const float4*)&As[kk][ty * 8];
            float4 a1 = *(const float4*)&As[kk][ty * 8 + 4];
            float4 b0 = *(const float4*)&Bs[kk][tx * 8];
            float4 b1 = *(const float4*)&Bs[kk][tx * 8 + 4];
            float ra[8] = {a0.x, a0.y, a0.z, a0.w, a1.x, a1.y, a1.z, a1.w};
            float rb[8] = {b0.x, b0.y, b0.z, b0.w, b1.x, b1.y, b1.z, b1.w};
#pragma unroll
            for (int i = 0; i < 8; i++)
#pragma unroll
                for (int j = 0; j < 8; j++)
                    acc[i][j] = fmaf(ra[i], rb[j], acc[i][j]);
        }
        __syncthreads();
    }

#pragma unroll
    for (int i = 0; i < 8; i++) {
        const size_t m = (size_t)(m0 + ty * 8 + i);
#pragma unroll
        for (int j = 0; j < 8; j += 4) {
            int n = n0 + tx * 8 + j;
            float4 o;
            o.x = acc[i][j + 0] + bias[n + 0];
            o.y = acc[i][j + 1] + bias[n + 1];
            o.z = acc[i][j + 2] + bias[n + 2];
            o.w = acc[i][j + 3] + bias[n + 3];
            *(float4*)&g_y[m * N_TOTAL + n] = o;
        }
    }
}

// ---------------------------------------------------------------------------
// Kernel 2: in-place L2 normalization of q and k rows (128 elems each).
// One warp per row; rows = M_TOTAL * NH * 2 = 262144.
// ---------------------------------------------------------------------------
__global__ __launch_bounds__(256) void l2norm_qk_kernel()
{
    int warp = (blockIdx.x * blockDim.x + threadIdx.x) >> 5;
    int lane = threadIdx.x & 31;
    int m   = warp >> 5;        // row of y
    int r   = warp & 31;        // h*2 + sel
    int h   = r >> 1;
    int sel = r & 1;

    float* p = &g_y[(size_t)m * N_TOTAL + h * (3 * HD) + sel * HD];
    float4 v = *(float4*)&p[lane * 4];
    float s = v.x * v.x + v.y * v.y + v.z * v.z + v.w * v.w;
#pragma unroll
    for (int o = 16; o > 0; o >>= 1) s += __shfl_xor_sync(0xffffffffu, s, o);
    float scale = 1.0f / fmaxf(sqrtf(s), 1e-12f);
    v.x *= scale; v.y *= scale; v.z *= scale; v.w *= scale;
    *(float4*)&p[lane * 4] = v;
}

// ---------------------------------------------------------------------------
// Kernel 3: flash attention (non-causal, scale=1), fp32.
// Block: 64 query rows of one (b,h). 256 threads = 16x16.
// Per thread: 4x4 score fragment, 4x8 output fragment.
// ---------------------------------------------------------------------------
#define ATT_SMEM_FLOATS (64 * 132 * 3 + 64 * 68)

__global__ __launch_bounds__(256) void attention_kernel(float* __restrict__ out)
{
    extern __shared__ __align__(16) float sm[];
    float* Qs = sm;                    // [64][132]
    float* Kt = sm + 64 * 132;         // [64][132]
    float* Vs = sm + 2 * 64 * 132;     // [64][132]
    float* Ps = sm + 3 * 64 * 132;     // [64][68]

    const int tid = threadIdx.x;
    const int tx  = tid & 15;
    const int ty  = tid >> 4;
    const int m0  = blockIdx.x * 64;
    const int bh  = blockIdx.y;
    const int bb  = bh >> 4;     // / NH
    const int h   = bh & 15;
    const size_t head_base =
        (size_t)bb * L_SEQ * N_TOTAL + (size_t)h * (3 * HD);

    // Load Q tile (already L2-normalized in g_y)
#pragma unroll
    for (int u = 0; u < 8; u++) {
        int idx = u * 256 + tid;       // float4 id in [0,2048)
        int row = idx >> 5;
        int d   = (idx & 31) << 2;
        float4 v = *(const float4*)&g_y[head_base + (size_t)(m0 + row) * N_TOTAL + d];
        *(float4*)&Qs[row * 132 + d] = v;
    }

    float o[4][8];
    float m_row[4], l_row[4];
#pragma unroll
    for (int i = 0; i < 4; i++) {
        m_row[i] = -1e30f; l_row[i] = 0.f;
#pragma unroll
        for (int c = 0; c < 8; c++) o[i][c] = 0.f;
    }
    __syncthreads();

    for (int n0 = 0; n0 < L_SEQ; n0 += 64) {
        // Load K, V tiles (coalesced along d)
#pragma unroll
        for (int u = 0; u < 8; u++) {
            int idx = u * 256 + tid;
            int row = idx >> 5;
            int d   = (idx & 31) << 2;
            size_t g = head_base + (size_t)(n0 + row) * N_TOTAL + d;
            *(float4*)&Kt[row * 132 + d] = *(const float4*)&g_y[g + HD];
            *(float4*)&Vs[row * 132 + d] = *(const float4*)&g_y[g + 2 * HD];
        }
        __syncthreads();

        // S = Q . K^T  (4x4 fragment per thread)
        float s[4][4];
#pragma unroll
        for (int i = 0; i < 4; i++)
#pragma unroll
            for (int j = 0; j < 4; j++) s[i][j] = 0.f;

#pragma unroll 4
        for (int d = 0; d < HD; d += 4) {
            float4 q[4], k[4];
#pragma unroll
            for (int i = 0; i < 4; i++)
                q[i] = *(const float4*)&Qs[(ty * 4 + i) * 132 + d];
#pragma unroll
            for (int j = 0; j < 4; j++)
                k[j] = *(const float4*)&Kt[(tx * 4 + j) * 132 + d];
#pragma unroll
            for (int i = 0; i < 4; i++)
#pragma unroll
                for (int j = 0; j < 4; j++) {
                    s[i][j] = fmaf(q[i].x, k[j].x, s[i][j]);
                    s[i][j] = fmaf(q[i].y, k[j].y, s[i][j]);
                    s[i][j] = fmaf(q[i].z, k[j].z, s[i][j]);
                    s[i][j] = fmaf(q[i].w, k[j].w, s[i][j]);
                }
        }

        // Online softmax. Row owners = 16 lanes with same ty within warp.
#pragma unroll
        for (int i = 0; i < 4; i++) {
            float mx = fmaxf(fmaxf(s[i][0], s[i][1]), fmaxf(s[i][2], s[i][3]));
#pragma unroll
            for (int w = 1; w < 16; w <<= 1)
                mx = fmaxf(mx, __shfl_xor_sync(0xffffffffu, mx, w));
            float mnew  = fmaxf(m_row[i], mx);
            float alpha = __expf(m_row[i] - mnew);
            float rs = 0.f;
#pragma unroll
            for (int j = 0; j < 4; j++) {
                float p = __expf(s[i][j] - mnew);
                s[i][j] = p;
                rs += p;
            }
#pragma unroll
            for (int w = 1; w < 16; w <<= 1)
                rs += __shfl_xor_sync(0xffffffffu, rs, w);
            l_row[i] = l_row[i] * alpha + rs;
            m_row[i] = mnew;
#pragma unroll
            for (int c = 0; c < 8; c++) o[i][c] *= alpha;
            *(float4*)&Ps[(ty * 4 + i) * 68 + tx * 4] =
                make_float4(s[i][0], s[i][1], s[i][2], s[i][3]);
        }
        __syncthreads();

        // O += P @ V  (cols tx*8..tx*8+7)
#pragma unroll 8
        for (int n = 0; n < 64; n++) {
            float4 va = *(const float4*)&Vs[n * 132 + tx * 8];
            float4 vb = *(const float4*)&Vs[n * 132 + tx * 8 + 4];
#pragma unroll
            for (int i = 0; i < 4; i++) {
                float p = Ps[(ty * 4 + i) * 68 + n];
                o[i][0] = fmaf(p, va.x, o[i][0]);
                o[i][1] = fmaf(p, va.y, o[i][1]);
                o[i][2] = fmaf(p, va.z, o[i][2]);
                o[i][3] = fmaf(p, va.w, o[i][3]);
                o[i][4] = fmaf(p, vb.x, o[i][4]);
                o[i][5] = fmaf(p, vb.y, o[i][5]);
                o[i][6] = fmaf(p, vb.z, o[i][6]);
                o[i][7] = fmaf(p, vb.w, o[i][7]);
            }
        }
        __syncthreads();
    }

    // Epilogue: normalize by l and store to [B, L, H, HD] layout
#pragma unroll
    for (int i = 0; i < 4; i++) {
        float inv = 1.0f / l_row[i];
        int m = m0 + ty * 4 + i;
        float* op = &out[((size_t)(bb * L_SEQ + m)) * E_DIM + h * HD + tx * 8];
        *(float4*)&op[0] = make_float4(o[i][0] * inv, o[i][1] * inv,
                                       o[i][2] * inv, o[i][3] * inv);
        *(float4*)&op[4] = make_float4(o[i][4] * inv, o[i][5] * inv,
                                       o[i][6] * inv, o[i][7] * inv);
    }
}

// ---------------------------------------------------------------------------
extern "C" void kernel_launch(void* const* d_in, const int* in_sizes, int n_in,
                              void* d_out, int out_size)
{
    (void)in_sizes; (void)n_in; (void)out_size;
    const float* x = (const float*)d_in[0];
    const float* W = (const float*)d_in[1];
    const float* b = (const float*)d_in[2];
    float* out = (float*)d_out;

    // 1) QKV projection into scratch
    qkv_gemm_kernel<<<dim3(N_TOTAL / 128, M_TOTAL / 128), 256>>>(x, W, b);

    // 2) L2-normalize q and k rows in place (one warp per 128-elem row)
    l2norm_qk_kernel<<<(M_TOTAL * NH * 2) / 8, 256>>>();

    // 3) Flash attention, writes final [B, L, E] output
    size_t shm = (size_t)ATT_SMEM_FLOATS * sizeof(float);   // 118784 B
    cudaFuncSetAttribute(attention_kernel,
                         cudaFuncAttributeMaxDynamicSharedMemorySize, (int)shm);
    attention_kernel<<<dim3(L_SEQ / 64, B_SZ * NH), 256, shm>>>(out);
}

// round 3
// speedup vs baseline: 4.1466x; 4.1466x over previous
#include <cuda_runtime.h>
#include <math.h>
#include <stdint.h>

#define B_SZ   4
#define L_SEQ  2048
#define E_DIM  2048
#define NH     16
#define HD     128
#define M_TOTAL (B_SZ * L_SEQ)   /* 8192 */
#define K_DIM   E_DIM            /* 2048 */
#define N_TOTAL (3 * E_DIM)      /* 6144 */

// Scratch for QKV projection output: [M_TOTAL][N_TOTAL] fp32 (~201 MB).
__device__ float g_y[(size_t)M_TOTAL * (size_t)N_TOTAL];

// ---------------------------------------------------------------------------
// tf32 mma.sync helpers (sm_80+ family path — works at plain sm_103 target)
// ---------------------------------------------------------------------------
__device__ __forceinline__ uint32_t f2tf32(float f) {
    uint32_t r;
    asm("cvt.rna.tf32.f32 %0, %1;" : "=r"(r) : "f"(f));
    return r;
}

#define MMA_TF32(c, a0, a1, a2, a3, b0, b1)                                   \
    asm volatile(                                                             \
        "mma.sync.aligned.m16n8k8.row.col.f32.tf32.tf32.f32 "                 \
        "{%0,%1,%2,%3}, {%4,%5,%6,%7}, {%8,%9}, {%0,%1,%2,%3};"               \
        : "+f"((c)[0]), "+f"((c)[1]), "+f"((c)[2]), "+f"((c)[3])              \
        : "r"(a0), "r"(a1), "r"(a2), "r"(a3), "r"(b0), "r"(b1))

__device__ __forceinline__ uint32_t fu(float f) { return __float_as_uint(f); }

// ===========================================================================
// Kernel 1: QKV GEMM via mma.sync tf32.  y = x @ W^T + b
// CTA 128x128, BK=32, 8 warps (warp tile 32x64), double-buffered smem,
// padded row stride 36 floats (conflict-free fragment loads).
// ===========================================================================
#define GSTR 36
#define GEMM_SMEM_FLOATS (4 * 128 * GSTR)   /* A0,B0,A1,B1 */

__global__ __launch_bounds__(256) void qkv_gemm_mma(
    const float* __restrict__ A,      // [M_TOTAL][K_DIM]
    const float* __restrict__ Wt,     // [N_TOTAL][K_DIM]
    const float* __restrict__ bias)   // [N_TOTAL]
{
    extern __shared__ __align__(16) float gs[];
    float* Abuf[2] = {gs,                gs + 2 * 128 * GSTR};
    float* Bbuf[2] = {gs + 128 * GSTR,   gs + 3 * 128 * GSTR};

    const int tid  = threadIdx.x;
    const int lane = tid & 31;
    const int wid  = tid >> 5;
    const int gid  = lane >> 2;
    const int tig  = lane & 3;
    const int wm   = wid & 3;          // warp row block (32 rows)
    const int wn   = wid >> 2;         // warp col block (64 cols)
    const int m0   = blockIdx.y * 128;
    const int n0   = blockIdx.x * 128;

    float C[2][8][4];
#pragma unroll
    for (int t = 0; t < 2; t++)
#pragma unroll
        for (int u = 0; u < 8; u++)
#pragma unroll
            for (int j = 0; j < 4; j++) C[t][u][j] = 0.f;

    float4 ar[4], br[4];

    // ---- prologue: load tile 0 ----
#pragma unroll
    for (int u = 0; u < 4; u++) {
        int id = u * 256 + tid;
        int r  = id >> 3;
        int c  = (id & 7) << 2;
        ar[u] = *(const float4*)&A [(size_t)(m0 + r) * K_DIM + c];
        br[u] = *(const float4*)&Wt[(size_t)(n0 + r) * K_DIM + c];
    }
#pragma unroll
    for (int u = 0; u < 4; u++) {
        int id = u * 256 + tid;
        int r  = id >> 3;
        int c  = (id & 7) << 2;
        uint4 ta = make_uint4(f2tf32(ar[u].x), f2tf32(ar[u].y),
                              f2tf32(ar[u].z), f2tf32(ar[u].w));
        uint4 tb = make_uint4(f2tf32(br[u].x), f2tf32(br[u].y),
                              f2tf32(br[u].z), f2tf32(br[u].w));
        *(uint4*)&Abuf[0][r * GSTR + c] = ta;
        *(uint4*)&Bbuf[0][r * GSTR + c] = tb;
    }
    __syncthreads();

    const int NIT = K_DIM / 32;   // 64
    for (int it = 0; it < NIT; ++it) {
        const int cur = it & 1;
        const int nxt = cur ^ 1;
        const bool more = (it + 1 < NIT);

        if (more) {
            const int k0 = (it + 1) * 32;
#pragma unroll
            for (int u = 0; u < 4; u++) {
                int id = u * 256 + tid;
                int r  = id >> 3;
                int c  = (id & 7) << 2;
                ar[u] = *(const float4*)&A [(size_t)(m0 + r) * K_DIM + k0 + c];
                br[u] = *(const float4*)&Wt[(size_t)(n0 + r) * K_DIM + k0 + c];
            }
        }

        // ---- compute on cur buffer ----
        const float* Ab = Abuf[cur] + (wm * 32 + gid) * GSTR + tig;
        const float* Bb = Bbuf[cur] + (wn * 64 + gid) * GSTR + tig;
#pragma unroll
        for (int s = 0; s < 4; s++) {
            uint32_t a[2][4];
#pragma unroll
            for (int t = 0; t < 2; t++) {
                const float* p = Ab + t * 16 * GSTR + s * 8;
                a[t][0] = fu(p[0]);
                a[t][1] = fu(p[8 * GSTR]);
                a[t][2] = fu(p[4]);
                a[t][3] = fu(p[8 * GSTR + 4]);
            }
#pragma unroll
            for (int u = 0; u < 8; u++) {
                const float* p = Bb + u * 8 * GSTR + s * 8;
                uint32_t b0 = fu(p[0]);
                uint32_t b1 = fu(p[4]);
                MMA_TF32(C[0][u], a[0][0], a[0][1], a[0][2], a[0][3], b0, b1);
                MMA_TF32(C[1][u], a[1][0], a[1][1], a[1][2], a[1][3], b0, b1);
            }
        }
        __syncthreads();

        if (more) {
#pragma unroll
            for (int u = 0; u < 4; u++) {
                int id = u * 256 + tid;
                int r  = id >> 3;
                int c  = (id & 7) << 2;
                uint4 ta = make_uint4(f2tf32(ar[u].x), f2tf32(ar[u].y),
                                      f2tf32(ar[u].z), f2tf32(ar[u].w));
                uint4 tb = make_uint4(f2tf32(br[u].x), f2tf32(br[u].y),
                                      f2tf32(br[u].z), f2tf32(br[u].w));
                *(uint4*)&Abuf[nxt][r * GSTR + c] = ta;
                *(uint4*)&Bbuf[nxt][r * GSTR + c] = tb;
            }
            __syncthreads();
        }
    }

    // ---- epilogue: add bias, store ----
#pragma unroll
    for (int t = 0; t < 2; t++) {
        int r0 = m0 + wm * 32 + t * 16 + gid;
#pragma unroll
        for (int u = 0; u < 8; u++) {
            int col = n0 + wn * 64 + u * 8 + tig * 2;
            float2 bv = *(const float2*)&bias[col];
            float2 v0 = make_float2(C[t][u][0] + bv.x, C[t][u][1] + bv.y);
            float2 v1 = make_float2(C[t][u][2] + bv.x, C[t][u][3] + bv.y);
            *(float2*)&g_y[(size_t)r0 * N_TOTAL + col]       = v0;
            *(float2*)&g_y[(size_t)(r0 + 8) * N_TOTAL + col] = v1;
        }
    }
}

// ===========================================================================
// Kernel 2: in-place L2 normalization of q and k rows (128 elems each).
// ===========================================================================
__global__ __launch_bounds__(256) void l2norm_qk_kernel()
{
    int warp = (blockIdx.x * blockDim.x + threadIdx.x) >> 5;
    int lane = threadIdx.x & 31;
    int m   = warp >> 5;
    int r   = warp & 31;
    int h   = r >> 1;
    int sel = r & 1;

    float* p = &g_y[(size_t)m * N_TOTAL + h * (3 * HD) + sel * HD];
    float4 v = *(float4*)&p[lane * 4];
    float s = v.x * v.x + v.y * v.y + v.z * v.z + v.w * v.w;
#pragma unroll
    for (int o = 16; o > 0; o >>= 1) s += __shfl_xor_sync(0xffffffffu, s, o);
    float scale = 1.0f / fmaxf(sqrtf(s), 1e-12f);
    v.x *= scale; v.y *= scale; v.z *= scale; v.w *= scale;
    *(float4*)&p[lane * 4] = v;
}

// ===========================================================================
// Kernel 3: attention via mma.sync tf32.
// BM=128 (8 warps x 16 rows), BN=64 KV tiles. Scores in [-1,1] => no
// running max / rescale; exp via polynomial; O accumulates in mma C-regs.
// ===========================================================================
#define QSTR 132   /* 132 % 32 == 4 -> conflict-free A/B frag loads */
#define KSTR 132
#define VSTR 136   /* 136 % 32 == 8 -> conflict-free V B-frag loads */
#define PSTR 68    /* 68  % 32 == 4 */
#define ATT_SMEM_FLOATS (128 * QSTR + 64 * KSTR + 64 * VSTR + 128 * PSTR)

__device__ __forceinline__ float exp_poly(float x) {
    float p = fmaf(x, 2.48015873e-5f, 1.98412698e-4f);
    p = fmaf(x, p, 1.38888889e-3f);
    p = fmaf(x, p, 8.33333333e-3f);
    p = fmaf(x, p, 4.16666667e-2f);
    p = fmaf(x, p, 1.66666667e-1f);
    p = fmaf(x, p, 0.5f);
    p = fmaf(x, p, 1.0f);
    p = fmaf(x, p, 1.0f);
    return p;
}

__global__ __launch_bounds__(256) void attn_mma_kernel(float* __restrict__ out)
{
    extern __shared__ __align__(16) float sm[];
    float* Qs = sm;
    float* Ks = Qs + 128 * QSTR;
    float* Vs = Ks + 64 * KSTR;
    float* Ps = Vs + 64 * VSTR;

    const int tid  = threadIdx.x;
    const int lane = tid & 31;
    const int wid  = tid >> 5;
    const int gid  = lane >> 2;
    const int tig  = lane & 3;
    const int rbase = wid * 16;
    const int m0   = blockIdx.x * 128;
    const int bh   = blockIdx.y;
    const int bb   = bh >> 4;
    const int h    = bh & 15;
    const size_t head_base =
        (size_t)bb * L_SEQ * N_TOTAL + (size_t)h * (3 * HD);

    // Load + cvt Q tile [128][128]
#pragma unroll
    for (int u = 0; u < 16; u++) {
        int id = u * 256 + tid;
        int r  = id >> 5;
        int c  = (id & 31) << 2;
        float4 v = *(const float4*)&g_y[head_base + (size_t)(m0 + r) * N_TOTAL + c];
        *(uint4*)&Qs[r * QSTR + c] = make_uint4(f2tf32(v.x), f2tf32(v.y),
                                                f2tf32(v.z), f2tf32(v.w));
    }

    float O[16][4];
#pragma unroll
    for (int u = 0; u < 16; u++)
#pragma unroll
        for (int j = 0; j < 4; j++) O[u][j] = 0.f;
    float l0 = 0.f, l1 = 0.f;
    __syncthreads();

    for (int n0t = 0; n0t < L_SEQ; n0t += 64) {
        // Load + cvt K, V tiles [64][128]
#pragma unroll
        for (int u = 0; u < 8; u++) {
            int id = u * 256 + tid;
            int r  = id >> 5;
            int c  = (id & 31) << 2;
            size_t g = head_base + (size_t)(n0t + r) * N_TOTAL + c;
            float4 kv = *(const float4*)&g_y[g + HD];
            float4 vv = *(const float4*)&g_y[g + 2 * HD];
            *(uint4*)&Ks[r * KSTR + c] = make_uint4(f2tf32(kv.x), f2tf32(kv.y),
                                                    f2tf32(kv.z), f2tf32(kv.w));
            *(uint4*)&Vs[r * VSTR + c] = make_uint4(f2tf32(vv.x), f2tf32(vv.y),
                                                    f2tf32(vv.z), f2tf32(vv.w));
        }
        __syncthreads();

        // ---- S = Q . K^T ----
        float S[8][4];
#pragma unroll
        for (int u = 0; u < 8; u++)
#pragma unroll
            for (int j = 0; j < 4; j++) S[u][j] = 0.f;

        const float* Qb = Qs + (rbase + gid) * QSTR + tig;
        const float* Kb = Ks + gid * KSTR + tig;
#pragma unroll
        for (int s = 0; s < 16; s++) {
            uint32_t a0 = fu(Qb[s * 8]);
            uint32_t a1 = fu(Qb[8 * QSTR + s * 8]);
            uint32_t a2 = fu(Qb[s * 8 + 4]);
            uint32_t a3 = fu(Qb[8 * QSTR + s * 8 + 4]);
#pragma unroll
            for (int u = 0; u < 8; u++) {
                uint32_t b0 = fu(Kb[u * 8 * KSTR + s * 8]);
                uint32_t b1 = fu(Kb[u * 8 * KSTR + s * 8 + 4]);
                MMA_TF32(S[u], a0, a1, a2, a3, b0, b1);
            }
        }

        // ---- exp + l accumulate + stage P (tf32) ----
#pragma unroll
        for (int u = 0; u < 8; u++) {
            float p0 = exp_poly(S[u][0]);
            float p1 = exp_poly(S[u][1]);
            float p2 = exp_poly(S[u][2]);
            float p3 = exp_poly(S[u][3]);
            l0 += p0 + p1;
            l1 += p2 + p3;
            *(uint2*)&Ps[(rbase + gid) * PSTR + u * 8 + tig * 2] =
                make_uint2(f2tf32(p0), f2tf32(p1));
            *(uint2*)&Ps[(rbase + 8 + gid) * PSTR + u * 8 + tig * 2] =
                make_uint2(f2tf32(p2), f2tf32(p3));
        }
        __syncwarp();

        // ---- O += P . V ----
        const float* Pb = Ps + (rbase + gid) * PSTR + tig;
        const float* Vb = Vs + tig * VSTR + gid;
#pragma unroll
        for (int s = 0; s < 8; s++) {
            uint32_t a0 = fu(Pb[s * 8]);
            uint32_t a1 = fu(Pb[8 * PSTR + s * 8]);
            uint32_t a2 = fu(Pb[s * 8 + 4]);
            uint32_t a3 = fu(Pb[8 * PSTR + s * 8 + 4]);
#pragma unroll
            for (int ud = 0; ud < 16; ud++) {
                uint32_t b0 = fu(Vb[s * 8 * VSTR + ud * 8]);
                uint32_t b1 = fu(Vb[(s * 8 + 4) * VSTR + ud * 8]);
                MMA_TF32(O[ud], a0, a1, a2, a3, b0, b1);
            }
        }
        __syncthreads();
    }

    // ---- epilogue: reduce l over the 4 lanes of each row group, store ----
    l0 += __shfl_xor_sync(0xffffffffu, l0, 1);
    l0 += __shfl_xor_sync(0xffffffffu, l0, 2);
    l1 += __shfl_xor_sync(0xffffffffu, l1, 1);
    l1 += __shfl_xor_sync(0xffffffffu, l1, 2);
    const float inv0 = 1.0f / l0;
    const float inv1 = 1.0f / l1;

    const int r0 = m0 + rbase + gid;
    float* o0 = &out[((size_t)(bb * L_SEQ + r0)) * E_DIM + h * HD];
    float* o1 = &out[((size_t)(bb * L_SEQ + r0 + 8)) * E_DIM + h * HD];
#pragma unroll
    for (int ud = 0; ud < 16; ud++) {
        int col = ud * 8 + tig * 2;
        *(float2*)&o0[col] = make_float2(O[ud][0] * inv0, O[ud][1] * inv0);
        *(float2*)&o1[col] = make_float2(O[ud][2] * inv1, O[ud][3] * inv1);
    }
}

// ===========================================================================
extern "C" void kernel_launch(void* const* d_in, const int* in_sizes, int n_in,
                              void* d_out, int out_size)
{
    (void)in_sizes; (void)n_in; (void)out_size;
    const float* x = (const float*)d_in[0];
    const float* W = (const float*)d_in[1];
    const float* b = (const float*)d_in[2];
    float* out = (float*)d_out;

    // 1) QKV projection (tensor cores via mma.sync tf32)
    size_t gsmem = (size_t)GEMM_SMEM_FLOATS * sizeof(float);   // 73728 B
    cudaFuncSetAttribute(qkv_gemm_mma,
                         cudaFuncAttributeMaxDynamicSharedMemorySize, (int)gsmem);
    qkv_gemm_mma<<<dim3(N_TOTAL / 128, M_TOTAL / 128), 256, gsmem>>>(x, W, b);

    // 2) L2-normalize q and k rows in place
    l2norm_qk_kernel<<<(M_TOTAL * NH * 2) / 8, 256>>>();

    // 3) Attention (tensor cores, bounded-score softmax)
    size_t asmem = (size_t)ATT_SMEM_FLOATS * sizeof(float);    // 171008 B
    cudaFuncSetAttribute(attn_mma_kernel,
                         cudaFuncAttributeMaxDynamicSharedMemorySize, (int)asmem);
    attn_mma_kernel<<<dim3(L_SEQ / 128, B_SZ * NH), 256, asmem>>>(out);
}

// round 4
// speedup vs baseline: 5.6536x; 1.3634x over previous
#include <cuda_runtime.h>
#include <math.h>
#include <stdint.h>

#define B_SZ   4
#define L_SEQ  2048
#define E_DIM  2048
#define NH     16
#define HD     128
#define M_TOTAL (B_SZ * L_SEQ)   /* 8192 */
#define K_DIM   E_DIM            /* 2048 */
#define N_TOTAL (3 * E_DIM)      /* 6144 */

// Scratch: QKV output + tf32-pre-rounded copies of x and W.
__device__ float g_y [(size_t)M_TOTAL * (size_t)N_TOTAL];   // ~201 MB
__device__ float g_xr[(size_t)M_TOTAL * (size_t)K_DIM];     // ~67 MB
__device__ float g_wr[(size_t)N_TOTAL * (size_t)K_DIM];     // ~50 MB

// ---------------------------------------------------------------------------
// PTX helpers
// ---------------------------------------------------------------------------
__device__ __forceinline__ uint32_t f2tf32(float f) {
    uint32_t r;
    asm("cvt.rna.tf32.f32 %0, %1;" : "=r"(r) : "f"(f));
    return r;
}
__device__ __forceinline__ uint32_t fu(float f) { return __float_as_uint(f); }

__device__ __forceinline__ uint32_t smem_u32(const void* p) {
    uint32_t a;
    asm("{ .reg .u64 t; cvta.to.shared.u64 t, %1; cvt.u32.u64 %0, t; }"
        : "=r"(a) : "l"(p));
    return a;
}

#define MMA_TF32(c, a0, a1, a2, a3, b0, b1)                                   \
    asm volatile(                                                             \
        "mma.sync.aligned.m16n8k8.row.col.f32.tf32.tf32.f32 "                 \
        "{%0,%1,%2,%3}, {%4,%5,%6,%7}, {%8,%9}, {%0,%1,%2,%3};"               \
        : "+f"((c)[0]), "+f"((c)[1]), "+f"((c)[2]), "+f"((c)[3])              \
        : "r"(a0), "r"(a1), "r"(a2), "r"(a3), "r"(b0), "r"(b1))

#define LDSM_X4(r0, r1, r2, r3, addr)                                         \
    asm volatile("ldmatrix.sync.aligned.m8n8.x4.shared.b16 "                  \
                 "{%0,%1,%2,%3}, [%4];"                                       \
                 : "=r"(r0), "=r"(r1), "=r"(r2), "=r"(r3) : "r"(addr))

#define CP_ASYNC16(dst, src)                                                  \
    asm volatile("cp.async.cg.shared.global [%0], [%1], 16;"                  \
                 :: "r"(dst), "l"(src))
#define CP_COMMIT() asm volatile("cp.async.commit_group;" ::: "memory")
#define CP_WAIT(n)  asm volatile("cp.async.wait_group %0;" :: "n"(n) : "memory")

// ===========================================================================
// Kernel 0: elementwise tf32 pre-round (x -> g_xr, W -> g_wr)
// ===========================================================================
__global__ __launch_bounds__(256) void preround_kernel(
    const float* __restrict__ src, float* __restrict__ dst, int n4)
{
    int i = blockIdx.x * blockDim.x + threadIdx.x;
    if (i >= n4) return;
    float4 v = ((const float4*)src)[i];
    float4 o;
    o.x = __uint_as_float(f2tf32(v.x));
    o.y = __uint_as_float(f2tf32(v.y));
    o.z = __uint_as_float(f2tf32(v.z));
    o.w = __uint_as_float(f2tf32(v.w));
    ((float4*)dst)[i] = o;
}

// ===========================================================================
// Kernel 1: QKV GEMM. 128x128 tile, BK=32, 3-stage cp.async, ldmatrix frags.
// 8 warps as 4(M) x 2(N): warp tile 32 x 64.
// ===========================================================================
#define GSTR 36
#define G_STAGE_F (2 * 128 * GSTR)   /* 9216 floats per stage (A then B) */
#define G_SMEM_BYTES (3 * G_STAGE_F * 4)

__global__ __launch_bounds__(256, 2) void qkv_gemm_v2(
    const float* __restrict__ bias)
{
    extern __shared__ __align__(16) float gs[];
    const uint32_t sbase = smem_u32(gs);

    const int tid  = threadIdx.x;
    const int lane = tid & 31;
    const int wid  = tid >> 5;
    const int gid  = lane >> 2;
    const int tig  = lane & 3;
    const int wm   = wid & 3;
    const int wn   = wid >> 2;
    const int m0   = blockIdx.y * 128;
    const int n0   = blockIdx.x * 128;

    // ldmatrix per-lane offsets (bytes)
    const uint32_t a_lm = (uint32_t)(((lane & 15) * GSTR + (lane >> 4) * 4) * 4);
    const uint32_t b_lm = (uint32_t)((((lane & 7) + (lane >> 4) * 8) * GSTR
                                      + ((lane >> 3) & 1) * 4) * 4);

    // cp.async per-thread source rows
    const int cp_r = tid >> 3;     // 0..31 (advances by 32 per i)
    const int cp_c = tid & 7;      // 16B chunk within row

    float C[2][8][4];
#pragma unroll
    for (int t = 0; t < 2; t++)
#pragma unroll
        for (int u = 0; u < 8; u++)
#pragma unroll
            for (int j = 0; j < 4; j++) C[t][u][j] = 0.f;

    const int NIT = K_DIM / 32;   // 64

    // ---- stage loader ----
    auto stage_load = [&](int it, int st) {
        const int k0 = it * 32;
        const uint32_t sb = sbase + (uint32_t)(st * G_STAGE_F * 4);
#pragma unroll
        for (int i = 0; i < 4; i++) {           // A: 128 rows
            int r = i * 32 + cp_r;
            uint32_t dst = sb + (uint32_t)((r * GSTR + cp_c * 4) * 4);
            const float* src = g_xr + (size_t)(m0 + r) * K_DIM + k0 + cp_c * 4;
            CP_ASYNC16(dst, src);
        }
#pragma unroll
        for (int i = 0; i < 4; i++) {           // B: 128 rows
            int r = i * 32 + cp_r;
            uint32_t dst = sb + (uint32_t)((4608 + r * GSTR + cp_c * 4) * 4);
            const float* src = g_wr + (size_t)(n0 + r) * K_DIM + k0 + cp_c * 4;
            CP_ASYNC16(dst, src);
        }
    };

    stage_load(0, 0); CP_COMMIT();
    stage_load(1, 1); CP_COMMIT();

    for (int it = 0; it < NIT; ++it) {
        CP_WAIT(1);
        __syncthreads();
        if (it + 2 < NIT) stage_load(it + 2, (it + 2) % 3);
        CP_COMMIT();

        const uint32_t sb = sbase + (uint32_t)(((it % 3) * G_STAGE_F) * 4);
        const uint32_t aB = sb + (uint32_t)(wm * 32 * GSTR * 4) + a_lm;
        const uint32_t bB = sb + (uint32_t)((4608 + wn * 64 * GSTR) * 4) + b_lm;

#pragma unroll
        for (int s = 0; s < 4; s++) {
            uint32_t a0[4], a1[4];
            LDSM_X4(a0[0], a0[1], a0[2], a0[3], aB + s * 32);
            LDSM_X4(a1[0], a1[1], a1[2], a1[3], aB + 16 * GSTR * 4 + s * 32);
#pragma unroll
            for (int up = 0; up < 4; up++) {
                uint32_t b[4];
                LDSM_X4(b[0], b[1], b[2], b[3],
                        bB + up * 16 * GSTR * 4 + s * 32);
                MMA_TF32(C[0][up * 2],     a0[0], a0[1], a0[2], a0[3], b[0], b[1]);
                MMA_TF32(C[0][up * 2 + 1], a0[0], a0[1], a0[2], a0[3], b[2], b[3]);
                MMA_TF32(C[1][up * 2],     a1[0], a1[1], a1[2], a1[3], b[0], b[1]);
                MMA_TF32(C[1][up * 2 + 1], a1[0], a1[1], a1[2], a1[3], b[2], b[3]);
            }
        }
    }

    // ---- epilogue: add bias, store ----
#pragma unroll
    for (int t = 0; t < 2; t++) {
        int r0 = m0 + wm * 32 + t * 16 + gid;
#pragma unroll
        for (int u = 0; u < 8; u++) {
            int col = n0 + wn * 64 + u * 8 + tig * 2;
            float2 bv = *(const float2*)&bias[col];
            *(float2*)&g_y[(size_t)r0 * N_TOTAL + col] =
                make_float2(C[t][u][0] + bv.x, C[t][u][1] + bv.y);
            *(float2*)&g_y[(size_t)(r0 + 8) * N_TOTAL + col] =
                make_float2(C[t][u][2] + bv.x, C[t][u][3] + bv.y);
        }
    }
}

// ===========================================================================
// Kernel 2: l2-normalize q,k rows; tf32-round q,k,v rows in place.
// One warp per (m, h, comp).
// ===========================================================================
__global__ __launch_bounds__(256) void l2norm_qkv_kernel()
{
    int w    = (blockIdx.x * blockDim.x + threadIdx.x) >> 5;
    int lane = threadIdx.x & 31;
    int m    = w / (NH * 3);
    int r    = w % (NH * 3);
    int h    = r / 3;
    int comp = r % 3;

    float* p = &g_y[(size_t)m * N_TOTAL + h * (3 * HD) + comp * HD];
    float4 v = *(float4*)&p[lane * 4];
    if (comp < 2) {
        float s = v.x * v.x + v.y * v.y + v.z * v.z + v.w * v.w;
#pragma unroll
        for (int o = 16; o > 0; o >>= 1) s += __shfl_xor_sync(0xffffffffu, s, o);
        float sc = 1.0f / fmaxf(sqrtf(s), 1e-12f);
        v.x *= sc; v.y *= sc; v.z *= sc; v.w *= sc;
    }
    float4 o;
    o.x = __uint_as_float(f2tf32(v.x));
    o.y = __uint_as_float(f2tf32(v.y));
    o.z = __uint_as_float(f2tf32(v.z));
    o.w = __uint_as_float(f2tf32(v.w));
    *(float4*)&p[lane * 4] = o;
}

// ===========================================================================
// Kernel 3: attention. BM=128 (8 warps x 16 rows), BN=64.
// Q fragments persistent in registers; K/V double-buffered via cp.async;
// K and P fragments via ldmatrix; bounded-score softmax (poly exp).
// ===========================================================================
#define KSTR 132
#define VSTR 136
#define PSTR 68
#define K_OFF(buf) ((buf) * (64 * KSTR))
#define V_OFF(buf) (2 * 64 * KSTR + (buf) * (64 * VSTR))
#define P_OFF      (2 * 64 * KSTR + 2 * 64 * VSTR)
#define ATT_SMEM_FLOATS (P_OFF + 128 * PSTR)

__device__ __forceinline__ float exp_poly(float x) {
    float p = fmaf(x, 2.48015873e-5f, 1.98412698e-4f);
    p = fmaf(x, p, 1.38888889e-3f);
    p = fmaf(x, p, 8.33333333e-3f);
    p = fmaf(x, p, 4.16666667e-2f);
    p = fmaf(x, p, 1.66666667e-1f);
    p = fmaf(x, p, 0.5f);
    p = fmaf(x, p, 1.0f);
    p = fmaf(x, p, 1.0f);
    return p;
}

__global__ __launch_bounds__(256, 1) void attn_v2(float* __restrict__ out)
{
    extern __shared__ __align__(16) float sm[];
    const uint32_t sbase = smem_u32(sm);

    const int tid  = threadIdx.x;
    const int lane = tid & 31;
    const int wid  = tid >> 5;
    const int gid  = lane >> 2;
    const int tig  = lane & 3;
    const int rbase = wid * 16;
    const int m0   = blockIdx.x * 128;
    const int bh   = blockIdx.y;
    const int bb   = bh >> 4;
    const int h    = bh & 15;
    const size_t head_base =
        (size_t)bb * L_SEQ * N_TOTAL + (size_t)h * (3 * HD);

    // ---- persistent Q fragments (rows rbase..rbase+15, all 128 d) ----
    uint32_t Qf[16][4];
    {
        const size_t rq = head_base + (size_t)(m0 + rbase + gid) * N_TOTAL;
#pragma unroll
        for (int s = 0; s < 16; s++) {
            int col = s * 8 + tig;
            Qf[s][0] = fu(g_y[rq + col]);
            Qf[s][1] = fu(g_y[rq + 8 * N_TOTAL + col]);
            Qf[s][2] = fu(g_y[rq + col + 4]);
            Qf[s][3] = fu(g_y[rq + 8 * N_TOTAL + col + 4]);
        }
    }

    // ldmatrix lane offsets (bytes)
    const uint32_t k_lm = (uint32_t)(((((lane & 7) + (lane >> 4) * 8) * KSTR)
                                      + ((lane >> 3) & 1) * 4) * 4);
    const uint32_t p_lm = sbase +
        (uint32_t)(((P_OFF + (rbase + (lane & 15)) * PSTR) + (lane >> 4) * 4) * 4);

    // cp.async per-thread pattern: rows wid + i*8, chunk tid&31
    const int cp_c = tid & 31;

    auto stage_load = [&](int tt, int buf) {
        const int n0t = tt * 64;
#pragma unroll
        for (int i = 0; i < 8; i++) {        // K
            int r = i * 8 + wid;
            uint32_t dst = sbase + (uint32_t)((K_OFF(buf) + r * KSTR + cp_c * 4) * 4);
            const float* src = g_y + head_base + (size_t)(n0t + r) * N_TOTAL
                               + HD + cp_c * 4;
            CP_ASYNC16(dst, src);
        }
#pragma unroll
        for (int i = 0; i < 8; i++) {        // V
            int r = i * 8 + wid;
            uint32_t dst = sbase + (uint32_t)((V_OFF(buf) + r * VSTR + cp_c * 4) * 4);
            const float* src = g_y + head_base + (size_t)(n0t + r) * N_TOTAL
                               + 2 * HD + cp_c * 4;
            CP_ASYNC16(dst, src);
        }
    };

    float O[16][4];
#pragma unroll
    for (int u = 0; u < 16; u++)
#pragma unroll
        for (int j = 0; j < 4; j++) O[u][j] = 0.f;
    float l0 = 0.f, l1 = 0.f;

    float* Ps = sm + P_OFF;

    stage_load(0, 0); CP_COMMIT();

    for (int tt = 0; tt < L_SEQ / 64; ++tt) {
        CP_WAIT(0);
        __syncthreads();
        if (tt + 1 < L_SEQ / 64) stage_load(tt + 1, (tt + 1) & 1);
        CP_COMMIT();

        const int buf = tt & 1;
        const uint32_t kB = sbase + (uint32_t)(K_OFF(buf) * 4) + k_lm;
        const float*   Vb = sm + V_OFF(buf) + tig * VSTR + gid;

        // ---- S = Q . K^T ----
        float S[8][4];
#pragma unroll
        for (int u = 0; u < 8; u++)
#pragma unroll
            for (int j = 0; j < 4; j++) S[u][j] = 0.f;

#pragma unroll
        for (int s = 0; s < 16; s++) {
#pragma unroll
            for (int up = 0; up < 4; up++) {
                uint32_t b[4];
                LDSM_X4(b[0], b[1], b[2], b[3],
                        kB + up * 16 * KSTR * 4 + s * 32);
                MMA_TF32(S[up * 2],     Qf[s][0], Qf[s][1], Qf[s][2], Qf[s][3],
                         b[0], b[1]);
                MMA_TF32(S[up * 2 + 1], Qf[s][0], Qf[s][1], Qf[s][2], Qf[s][3],
                         b[2], b[3]);
            }
        }

        // ---- exp, accumulate l, stage P (tf32) ----
#pragma unroll
        for (int u = 0; u < 8; u++) {
            float p0 = exp_poly(S[u][0]);
            float p1 = exp_poly(S[u][1]);
            float p2 = exp_poly(S[u][2]);
            float p3 = exp_poly(S[u][3]);
            l0 += p0 + p1;
            l1 += p2 + p3;
            *(uint2*)&Ps[(rbase + gid) * PSTR + u * 8 + tig * 2] =
                make_uint2(f2tf32(p0), f2tf32(p1));
            *(uint2*)&Ps[(rbase + 8 + gid) * PSTR + u * 8 + tig * 2] =
                make_uint2(f2tf32(p2), f2tf32(p3));
        }
        __syncwarp();

        // ---- O += P . V ----
#pragma unroll
        for (int s = 0; s < 8; s++) {
            uint32_t a[4];
            LDSM_X4(a[0], a[1], a[2], a[3], p_lm + s * 32);
#pragma unroll
            for (int ud = 0; ud < 16; ud++) {
                uint32_t b0 = fu(Vb[(s * 8) * VSTR + ud * 8]);
                uint32_t b1 = fu(Vb[(s * 8 + 4) * VSTR + ud * 8]);
                MMA_TF32(O[ud], a[0], a[1], a[2], a[3], b0, b1);
            }
        }
    }

    // ---- epilogue ----
    l0 += __shfl_xor_sync(0xffffffffu, l0, 1);
    l0 += __shfl_xor_sync(0xffffffffu, l0, 2);
    l1 += __shfl_xor_sync(0xffffffffu, l1, 1);
    l1 += __shfl_xor_sync(0xffffffffu, l1, 2);
    const float inv0 = 1.0f / l0;
    const float inv1 = 1.0f / l1;

    const int r0 = m0 + rbase + gid;
    float* o0 = &out[((size_t)(bb * L_SEQ + r0)) * E_DIM + h * HD];
    float* o1 = &out[((size_t)(bb * L_SEQ + r0 + 8)) * E_DIM + h * HD];
#pragma unroll
    for (int ud = 0; ud < 16; ud++) {
        int col = ud * 8 + tig * 2;
        *(float2*)&o0[col] = make_float2(O[ud][0] * inv0, O[ud][1] * inv0);
        *(float2*)&o1[col] = make_float2(O[ud][2] * inv1, O[ud][3] * inv1);
    }
}

// ===========================================================================
extern "C" void kernel_launch(void* const* d_in, const int* in_sizes, int n_in,
                              void* d_out, int out_size)
{
    (void)in_sizes; (void)n_in; (void)out_size;
    const float* x = (const float*)d_in[0];
    const float* W = (const float*)d_in[1];
    const float* b = (const float*)d_in[2];
    float* out = (float*)d_out;

    float* xr; cudaGetSymbolAddress((void**)&xr, g_xr);
    float* wr; cudaGetSymbolAddress((void**)&wr, g_wr);

    // 0) tf32 pre-round of x and W
    int nx4 = (M_TOTAL * K_DIM) / 4;
    int nw4 = (N_TOTAL * K_DIM) / 4;
    preround_kernel<<<(nx4 + 255) / 256, 256>>>(x, xr, nx4);
    preround_kernel<<<(nw4 + 255) / 256, 256>>>(W, wr, nw4);

    // 1) QKV projection (cp.async + ldmatrix + mma tf32)
    cudaFuncSetAttribute(qkv_gemm_v2,
                         cudaFuncAttributeMaxDynamicSharedMemorySize, G_SMEM_BYTES);
    qkv_gemm_v2<<<dim3(N_TOTAL / 128, M_TOTAL / 128), 256, G_SMEM_BYTES>>>(b);

    // 2) L2-normalize q,k + tf32-round q,k,v
    l2norm_qkv_kernel<<<(M_TOTAL * NH * 3) / 8, 256>>>();

    // 3) Attention
    size_t asmem = (size_t)ATT_SMEM_FLOATS * sizeof(float);
    cudaFuncSetAttribute(attn_v2,
                         cudaFuncAttributeMaxDynamicSharedMemorySize, (int)asmem);
    attn_v2<<<dim3(L_SEQ / 128, B_SZ * NH), 256, asmem>>>(out);
}